// round 4
// baseline (speedup 1.0000x reference)
#include <cuda_runtime.h>

#define T_LEN 200
#define B_SZ  1024
#define D_SZ  128
#define G3    384
#define RB    8
#define WSTR  130

// Precomputed x-side: [T*B][384] = (xWau+bau | xWar+bar | xWac+bac)
// Device global: allocated at module load, not by kernel_launch (guard-safe).
__device__ float g_X[(size_t)T_LEN * B_SZ * G3];

// ---------- packed fp32 helpers (Blackwell f32x2) ----------
__device__ __forceinline__ void fma2(unsigned long long &d,
                                     unsigned long long a,
                                     unsigned long long b) {
    asm("fma.rn.f32x2 %0, %1, %2, %0;" : "+l"(d) : "l"(a), "l"(b));
}
__device__ __forceinline__ unsigned long long pack2(float x, float y) {
    unsigned long long r;
    asm("mov.b64 %0, {%1, %2};" : "=l"(r) : "f"(x), "f"(y));
    return r;
}
__device__ __forceinline__ void unpack2(unsigned long long v, float &lo, float &hi) {
    asm("mov.b64 {%0, %1}, %2;" : "=f"(lo), "=f"(hi) : "l"(v));
}
__device__ __forceinline__ float sum2(unsigned long long v) {
    float lo, hi; unpack2(v, lo, hi); return lo + hi;
}

// =====================================================================
// Kernel 1: X-side GEMM.  out[m][g*128+c] = bias_g[c] + sum_k x[m][k] Wg[k][c]
// M = T*B = 204800, N = 384 (gate chosen per 64-col tile), K = 128.
// 64x64 tile, 256 threads, 4x4 microtile, f32x2 packed FMA.
// =====================================================================
#define TM 64
#define TN 64
#define TK 64
#define ASTR 68
#define BSTR 68

__global__ __launch_bounds__(256) void gemm_x(
    const float* __restrict__ Xin,
    const float* __restrict__ Wau, const float* __restrict__ bau,
    const float* __restrict__ War, const float* __restrict__ bar,
    const float* __restrict__ Wac, const float* __restrict__ bac)
{
    __shared__ float As[TM * ASTR];
    __shared__ float Bs[TK * BSTR];

    const int tid = threadIdx.x;
    const int tx = tid & 15;
    const int ty = tid >> 4;
    const int m0 = blockIdx.x * TM;
    const int n0 = blockIdx.y * TN;
    const int gate = n0 >> 7;       // 0,1,2 (64-col tiles never cross a gate)
    const int cg = n0 & 127;        // column offset within the gate

    const float* W    = (gate == 0) ? Wau : ((gate == 1) ? War : Wac);
    const float* bias = (gate == 0) ? bau : ((gate == 1) ? bar : bac);

    unsigned long long acc[4][2];
    #pragma unroll
    for (int i = 0; i < 4; i++) { acc[i][0] = 0ULL; acc[i][1] = 0ULL; }

    for (int k0 = 0; k0 < D_SZ; k0 += TK) {
        // Load 64x64 A tile and 64x64 B tile, float4-vectorized.
        #pragma unroll
        for (int l = 0; l < 4; l++) {
            int idx = tid + l * 256;          // 0..1023 float4 slots
            int row = idx >> 4;
            int c4  = idx & 15;
            float4 av = *(const float4*)(Xin + (size_t)(m0 + row) * D_SZ + k0 + c4 * 4);
            *(float4*)(As + row * ASTR + c4 * 4) = av;
            float4 bv = *(const float4*)(W + (size_t)(k0 + row) * D_SZ + cg + c4 * 4);
            *(float4*)(Bs + row * BSTR + c4 * 4) = bv;
        }
        __syncthreads();

        #pragma unroll 16
        for (int kk = 0; kk < TK; kk++) {
            unsigned long long b0 = *(const unsigned long long*)(Bs + kk * BSTR + tx * 4);
            unsigned long long b1 = *(const unsigned long long*)(Bs + kk * BSTR + tx * 4 + 2);
            #pragma unroll
            for (int i = 0; i < 4; i++) {
                float a = As[(ty * 4 + i) * ASTR + kk];
                unsigned long long a2 = pack2(a, a);
                fma2(acc[i][0], a2, b0);
                fma2(acc[i][1], a2, b1);
            }
        }
        __syncthreads();
    }

    // Epilogue: add bias, store float4.
    float b0f = bias[cg + tx * 4 + 0];
    float b1f = bias[cg + tx * 4 + 1];
    float b2f = bias[cg + tx * 4 + 2];
    float b3f = bias[cg + tx * 4 + 3];
    #pragma unroll
    for (int i = 0; i < 4; i++) {
        int m = m0 + ty * 4 + i;
        float v0, v1, v2, v3;
        unpack2(acc[i][0], v0, v1);
        unpack2(acc[i][1], v2, v3);
        float4 o = make_float4(v0 + b0f, v1 + b1f, v2 + b2f, v3 + b3f);
        *(float4*)(g_X + (size_t)m * G3 + n0 + tx * 4) = o;
    }
}

// =====================================================================
// Kernel 2: recurrence. 128 blocks x 8 batch rows, 128 threads.
// Thread tid owns state column d=tid for all 8 rows (registers).
// Wb (u|r|c) transposed in smem [384][130] -> k-contiguous float2 loads
// (stride 130 => 64-bit LDS is conflict-free across half-warp phases).
// State double-buffered in smem for the s@Wb dot products.
// =====================================================================
extern __shared__ float smem_rec[];

__global__ __launch_bounds__(128, 1) void augru_rec(
    const float* __restrict__ state, const float* __restrict__ att,
    const float* __restrict__ mask,
    const float* __restrict__ Wbu, const float* __restrict__ Wbr,
    const float* __restrict__ Wbc,
    float* __restrict__ out)
{
    float* WsT = smem_rec;                     // [384][WSTR]
    float* sb  = smem_rec + G3 * WSTR;         // [2][RB][128]
    const int tid = threadIdx.x;
    const int b0 = blockIdx.x * RB;

    // Transposed weight load: coalesced gmem reads, 2-way-conflict STS.
    #pragma unroll
    for (int g = 0; g < 3; g++) {
        const float* W = (g == 0) ? Wbu : ((g == 1) ? Wbr : Wbc);
        for (int i = tid; i < D_SZ * D_SZ; i += 128) {
            int k = i >> 7;
            int n = i & 127;
            WsT[(g * 128 + n) * WSTR + k] = W[i];
        }
    }

    float s_reg[RB];
    #pragma unroll
    for (int r = 0; r < RB; r++) {
        s_reg[r] = state[(size_t)(b0 + r) * D_SZ + tid];
        sb[r * 128 + tid] = s_reg[r];
    }
    __syncthreads();

    const float* wu = WsT + (size_t)tid * WSTR;
    const float* wr = WsT + (size_t)(128 + tid) * WSTR;
    const float* wc = WsT + (size_t)(256 + tid) * WSTR;

    int cur = 0;
    for (int t = 0; t < T_LEN; t++) {
        // Prefetch x-side values + att/mask for this step (consumed after the
        // long dot-product loop -> DRAM latency hidden behind ~3k cyc of FMA).
        const float* Xt = g_X + ((size_t)t * B_SZ + b0) * G3;
        float xu[RB], xr[RB], xc[RB], am[RB], mm[RB];
        #pragma unroll
        for (int r = 0; r < RB; r++) {
            xu[r] = Xt[r * G3 + tid];
            xr[r] = Xt[r * G3 + 128 + tid];
            xc[r] = Xt[r * G3 + 256 + tid];
            am[r] = __ldg(att + (size_t)t * B_SZ + b0 + r);
            mm[r] = __ldg(mask + (size_t)(b0 + r) * T_LEN + t);
        }

        unsigned long long au[RB], ar[RB], ac[RB];
        #pragma unroll
        for (int r = 0; r < RB; r++) { au[r] = 0ULL; ar[r] = 0ULL; ac[r] = 0ULL; }

        const float* srow = sb + cur * (RB * 128);
        #pragma unroll 8
        for (int k2 = 0; k2 < 64; k2++) {
            unsigned long long w_u = *(const unsigned long long*)(wu + 2 * k2);
            unsigned long long w_r = *(const unsigned long long*)(wr + 2 * k2);
            unsigned long long w_c = *(const unsigned long long*)(wc + 2 * k2);
            #pragma unroll
            for (int r = 0; r < RB; r++) {
                unsigned long long s2 =
                    *(const unsigned long long*)(srow + r * 128 + 2 * k2);
                fma2(au[r], w_u, s2);
                fma2(ar[r], w_r, s2);
                fma2(ac[r], w_c, s2);
            }
        }

        const int nxt = cur ^ 1;
        float* dst = sb + nxt * (RB * 128);
        #pragma unroll
        for (int r = 0; r < RB; r++) {
            float hu = xu[r] + sum2(au[r]);
            float hr = xr[r] + sum2(ar[r]);
            float dc = sum2(ac[r]);
            float ug = 1.0f / (1.0f + expf(-hu));
            float rg = 1.0f / (1.0f + expf(-hr));
            float cd = tanhf(xc[r] + rg * dc);
            float ua = am[r] * ug;
            float sn = s_reg[r] + mm[r] * ua * (cd - s_reg[r]);
            s_reg[r] = sn;
            dst[r * 128 + tid] = sn;
        }
        cur = nxt;
        __syncthreads();
    }

    #pragma unroll
    for (int r = 0; r < RB; r++)
        out[(size_t)(b0 + r) * D_SZ + tid] = s_reg[r];
}

// =====================================================================
extern "C" void kernel_launch(void* const* d_in, const int* in_sizes, int n_in,
                              void* d_out, int out_size)
{
    const float* inputs = (const float*)d_in[0];
    const float* state  = (const float*)d_in[1];
    const float* att    = (const float*)d_in[2];
    const float* mask   = (const float*)d_in[3];
    // max_len may or may not be materialized as an input (int32 scalar).
    int w = (n_in >= 14) ? 5 : 4;
    const float* Wau = (const float*)d_in[w + 0];
    const float* bau = (const float*)d_in[w + 1];
    const float* Wbu = (const float*)d_in[w + 2];
    const float* War = (const float*)d_in[w + 3];
    const float* bar = (const float*)d_in[w + 4];
    const float* Wbr = (const float*)d_in[w + 5];
    const float* Wac = (const float*)d_in[w + 6];
    const float* bac = (const float*)d_in[w + 7];
    const float* Wbc = (const float*)d_in[w + 8];
    float* out = (float*)d_out;
    (void)in_sizes; (void)out_size;

    dim3 g1(T_LEN * B_SZ / TM, G3 / TN);   // (3200, 6)
    gemm_x<<<g1, 256>>>(inputs, Wau, bau, War, bar, Wac, bac);

    // Host-side attribute set (not a stream op -> graph-capture safe).
    size_t smem = (size_t)(G3 * WSTR + 2 * RB * 128) * sizeof(float); // 207,872 B
    cudaFuncSetAttribute(augru_rec, cudaFuncAttributeMaxDynamicSharedMemorySize,
                         (int)smem);
    augru_rec<<<B_SZ / RB, 128, smem>>>(state, att, mask, Wbu, Wbr, Wbc, out);
}